// round 15
// baseline (speedup 1.0000x reference)
#include <cuda_runtime.h>

// LSTM_53815940218945: B=8192, T=256, I=1, H=50, O=1, fp32.
//
// R12 = R11 with the W gate-stride bug fixed:
//   R11 read W fragments at (gate*2*HPAD + s)*HPAD past pW -> gate stride
//   5408 floats in a 2704-float-per-gate layout -> smem OOB -> illegal access.
//   Correct offset: (gate*HPAD + s)*HPAD on top of pW = sW + u0*HPAD.
//
// Design (validated through R6/R10 ncu):
//   - warp = 8 eIdx x 4 uIdx -> conflict-free smem geometry (W: 4 unique
//     16B addrs/warp, 8-way broadcast; h: 8 unique, 4-way broadcast).
//   - hidden padded to 52 units (zero rows) -> UT=26, 208 thr/CTA,
//     32 elements/CTA, 2 CTAs/SM, 256 blocks.
//   - double-buffered sH -> ONE __syncthreads per timestep.
//   - per-thread tile ME=4 elements x (4 gates x NU=2 units), packed
//     fma.rn.f32x2 along k; gates (i,f,g,o) all thread-local -> no shuffles.

#define T_LEN  256
#define HID    50
#define HPAD   52              // padded hidden (rows AND k)
#define ET     8               // e-threads (warp-aligned)
#define ME     4               // elements per thread
#define EPB    (ET*ME)         // 32 elements per CTA
#define NU     2
#define UT     (HPAD/NU)       // 26 u-threads
#define NTHR   (ET*UT)         // 208 threads
#define NROW   (4*NU)          // 8 gate rows per thread

// dynamic smem layout (floats)
#define FW     (4*HPAD*HPAD)   // 10816 floats = 43264 B
#define FHBUF  (EPB*HPAD)      // 1664 floats per h buffer
#define F_H0   FW
#define F_WL   (FW + 2*FHBUF)  // 14144
#define F_BL   (F_WL + HPAD)   // 14196
#define SM_TOT ((F_BL + 4) * 4)   // 56800 bytes

__device__ __forceinline__ float fast_ex2(float x) {
    float y; asm("ex2.approx.f32 %0, %1;" : "=f"(y) : "f"(x)); return y;
}
__device__ __forceinline__ float fast_rcp(float x) {
    float y; asm("rcp.approx.f32 %0, %1;" : "=f"(y) : "f"(x)); return y;
}
__device__ __forceinline__ void ffma2(unsigned long long& d,
                                      unsigned long long a,
                                      unsigned long long b) {
    asm("fma.rn.f32x2 %0, %1, %2, %0;" : "+l"(d) : "l"(a), "l"(b));
}
union U64F2 { unsigned long long u; float2 f; };

__global__ __launch_bounds__(NTHR, 2)
void lstm_r12_kernel(const float* __restrict__ x,
                     const float* __restrict__ W_ih,
                     const float* __restrict__ W_hh,
                     const float* __restrict__ b_ih,
                     const float* __restrict__ b_hh,
                     const float* __restrict__ W_lin,
                     const float* __restrict__ b_lin,
                     float* __restrict__ out, int B)
{
    extern __shared__ __align__(16) float sm[];
    float* sW  = sm;                 // [4*HPAD][HPAD], zero-padded
    float* sH  = sm + F_H0;          // 2 x [EPB][HPAD]
    float* sWl = sm + F_WL;
    float* sBl = sm + F_BL;

    const int tid = threadIdx.x;

    // ---- staging: padded W (row = gate*HPAD + u; zero where u>=50 || k>=50)
    for (int i = tid; i < FW; i += NTHR) {
        const int row  = i / HPAD;
        const int k    = i - row * HPAD;
        const int gate = row / HPAD;          // 0..3
        const int u    = row - gate * HPAD;   // 0..51
        sW[i] = (u < HID && k < HID) ? W_hh[(gate * HID + u) * HID + k] : 0.0f;
    }
    for (int i = tid; i < 2 * FHBUF; i += NTHR) sH[i] = 0.0f;
    if (tid < HPAD) sWl[tid] = (tid < HID) ? W_lin[tid] : 0.0f;
    if (tid == 0) sBl[0] = b_lin[0];
    __syncthreads();

    const int eIdx = tid & (ET - 1);   // 0..7  (warp = 8e x 4u)
    const int uIdx = tid >> 3;         // 0..25
    const int u0   = uIdx * NU;

    // per-thread gate-row constants (zero for padded units)
    float biasR[NROW], wihR[NROW];
#pragma unroll
    for (int r = 0; r < NROW; r++) {
        const int gate = r >> 1, s = r & 1;
        const int uu = u0 + s;
        if (uu < HID) {
            const int row = gate * HID + uu;
            biasR[r] = b_ih[row] + b_hh[row];
            wihR[r]  = W_ih[row];          // I=1
        } else { biasR[r] = 0.0f; wihR[r] = 0.0f; }
    }

    // base pointers; other offsets are compile-time immediates
    const float* pW = sW + u0 * HPAD;      // + (gate*HPAD + s)*HPAD + 4*k4
    float*       pH = sH + eIdx * HPAD;    // + buf*FHBUF + m*ET*HPAD + 4*k4
    const size_t e0 = (size_t)blockIdx.x * EPB + eIdx;
    const float* pX = x + (e0 < (size_t)B ? e0 : 0) * T_LEN;
    bool valid[ME];
#pragma unroll
    for (int m = 0; m < ME; m++)
        valid[m] = (e0 + (size_t)m * ET) < (size_t)B;

    float c[ME][NU];
#pragma unroll
    for (int m = 0; m < ME; m++)
#pragma unroll
        for (int s = 0; s < NU; s++) c[m][s] = 0.0f;

    const float L2E = 1.4426950408889634f;

    for (int t = 0; t < T_LEN; t++) {
        const float* hin  = pH + (t & 1) * FHBUF;
        float*       hout = pH + ((t + 1) & 1) * FHBUF;

        float xv[ME];
#pragma unroll
        for (int m = 0; m < ME; m++)
            xv[m] = __ldg(pX + m * (ET * T_LEN) + (valid[m] ? t : 0));

        // ---- 8x4 register tile, packed f32x2 over k (13 float4 chunks) ----
        unsigned long long acc[NROW][ME];
#pragma unroll
        for (int r = 0; r < NROW; r++)
#pragma unroll
            for (int m = 0; m < ME; m++) acc[r][m] = 0ull;

#pragma unroll
        for (int k4 = 0; k4 < HPAD / 4; k4++) {
            ulonglong2 wv[NROW];
#pragma unroll
            for (int r = 0; r < NROW; r++) {
                const int gate = r >> 1, s = r & 1;
                wv[r] = *reinterpret_cast<const ulonglong2*>(
                    pW + (gate * HPAD + s) * HPAD + 4 * k4);   // FIXED stride
            }
#pragma unroll
            for (int m = 0; m < ME; m++) {
                const ulonglong2 hv = *reinterpret_cast<const ulonglong2*>(
                    hin + m * (ET * HPAD) + 4 * k4);
#pragma unroll
                for (int r = 0; r < NROW; r++) {
                    ffma2(acc[r][m], wv[r].x, hv.x);
                    ffma2(acc[r][m], wv[r].y, hv.y);
                }
            }
        }

        // ---- fold + activations + cell update (thread-local) ----
        float act[NROW][ME];
#pragma unroll
        for (int r = 0; r < NROW; r++) {
            const int gate = r >> 1;
            const float k1 = (gate == 2) ? (-2.0f * L2E) : (-L2E);
            const float am = (gate == 2) ? 2.0f : 1.0f;
            const float aa = (gate == 2) ? -1.0f : 0.0f;
#pragma unroll
            for (int m = 0; m < ME; m++) {
                U64F2 u; u.u = acc[r][m];
                const float pre = (u.f.x + u.f.y) + fmaf(xv[m], wihR[r], biasR[r]);
                const float e2 = fast_ex2(k1 * pre);
                const float rr = fast_rcp(1.0f + e2);
                act[r][m] = fmaf(am, rr, aa);
            }
        }
#pragma unroll
        for (int m = 0; m < ME; m++) {
            float2 hnew;
#pragma unroll
            for (int s = 0; s < NU; s++) {
                const float gi = act[0 * NU + s][m];
                const float gf = act[1 * NU + s][m];
                const float gg = act[2 * NU + s][m];
                const float go = act[3 * NU + s][m];
                const float cj = fmaf(gf, c[m][s], gi * gg);
                c[m][s] = cj;
                const float e2 = fast_ex2(-2.0f * L2E * cj);
                const float rr = fast_rcp(1.0f + e2);
                const float hj = go * fmaf(2.0f, rr, -1.0f);
                (s == 0 ? hnew.x : hnew.y) = hj;
            }
            *reinterpret_cast<float2*>(hout + m * (ET * HPAD) + u0) = hnew;
        }

        __syncthreads();   // one barrier per step (double-buffered sH)
    }

    // ---- head: h_T is in buffer (T_LEN & 1) == 0 ----
    if (tid < EPB) {
        const size_t ge = (size_t)blockIdx.x * EPB + tid;
        if (ge < (size_t)B) {
            const float* hrow = sH + tid * HPAD;   // buf 0
            float y = sBl[0];
#pragma unroll
            for (int j = 0; j < HID; j++) y = fmaf(hrow[j], sWl[j], y);
            out[ge] = y;
        }
    }
}

extern "C" void kernel_launch(void* const* d_in, const int* in_sizes, int n_in,
                              void* d_out, int out_size) {
    const float* x     = (const float*)d_in[0];
    const float* W_ih  = (const float*)d_in[1];
    const float* W_hh  = (const float*)d_in[2];
    const float* b_ih  = (const float*)d_in[3];
    const float* b_hh  = (const float*)d_in[4];
    const float* W_lin = (const float*)d_in[5];
    const float* b_lin = (const float*)d_in[6];
    float* out = (float*)d_out;

    const int B = out_size;                    // [B,1]
    const int blocks = (B + EPB - 1) / EPB;    // 256 for B=8192

    static int smem_set = 0;
    if (!smem_set) {
        cudaFuncSetAttribute(lstm_r12_kernel,
                             cudaFuncAttributeMaxDynamicSharedMemorySize,
                             SM_TOT);
        smem_set = 1;
    }
    lstm_r12_kernel<<<blocks, NTHR, SM_TOT>>>(x, W_ih, W_hh, b_ih, b_hh,
                                              W_lin, b_lin, out, B);
}

// round 16
// speedup vs baseline: 1.0803x; 1.0803x over previous
#include <cuda_runtime.h>

// LSTM_53815940218945: B=8192, T=256, I=1, H=50, O=1, fp32.
//
// R15: latency-bound fix. R12 showed fma=48%/issue=46% at 13 warps/SM ->
// convoy stalls, not pipe limits. Now: ONE 896-thread CTA per SM (grid=128),
// FOUR independent subgroups of 224 threads (ET=8 x UT=28, ME=2 -> 16
// elements each), per-subgroup named barriers so phases interleave across
// 28 warps/SM. Register-lean (acc=32, no act[] array, bias/Wih in smem)
// to fit the 73-reg/thread ceiling at 896 threads.
//
// Geometry (conflict-free, validated R6/R12):
//   W rows padded to 56/gate (UT=28 exact), k-width 52 -> warp W loads:
//   4 unique 16B addrs (banks 0,8,16,24). h row stride 60 -> 8 eIdx banks
//   0,28,24,20,16,12,8,4 all distinct. All v2/v4 accesses 8/16B aligned.

#define T_LEN 256
#define HID   50
#define KD    52            // k width (padded, float4-tiled)
#define RPAD  56            // row pad per gate (UT*NU)
#define HSTR  60            // h row stride (bank-clean for ET=8)
#define ET    8
#define ME    2
#define EPS   16            // elements per subgroup
#define UT    28
#define NU    2
#define SUBT  224           // threads per subgroup (7 warps, bar.sync-legal)
#define SUBS  4
#define NTHR  896
#define EPB   64            // elements per CTA
#define NROW  8

// smem layout (float offsets)
#define F_W    0
#define FW_SZ  (4*RPAD*KD)           // 11648
#define F_H    FW_SZ
#define FH_SUB (2*EPS*HSTR)          // 1920 per subgroup (2 buffers)
#define FH_SZ  (SUBS*FH_SUB)         // 7680
#define F_BIAS (F_H + FH_SZ)         // 19328
#define F_WIH  (F_BIAS + 4*RPAD)
#define F_WL   (F_WIH + 4*RPAD)
#define F_BL   (F_WL + 52)
#define SM_TOT ((F_BL + 4) * 4)      // ~79.3 KB dynamic smem

__device__ __forceinline__ float fast_ex2(float x) {
    float y; asm("ex2.approx.f32 %0, %1;" : "=f"(y) : "f"(x)); return y;
}
__device__ __forceinline__ float fast_rcp(float x) {
    float y; asm("rcp.approx.f32 %0, %1;" : "=f"(y) : "f"(x)); return y;
}
__device__ __forceinline__ void ffma2(unsigned long long& d,
                                      unsigned long long a,
                                      unsigned long long b) {
    asm("fma.rn.f32x2 %0, %1, %2, %0;" : "+l"(d) : "l"(a), "l"(b));
}
union U64F2 { unsigned long long u; float2 f; };

__global__ __launch_bounds__(NTHR, 1)
void lstm_r15_kernel(const float* __restrict__ x,
                     const float* __restrict__ W_ih,
                     const float* __restrict__ W_hh,
                     const float* __restrict__ b_ih,
                     const float* __restrict__ b_hh,
                     const float* __restrict__ W_lin,
                     const float* __restrict__ b_lin,
                     float* __restrict__ out, int B)
{
    extern __shared__ __align__(16) float sm[];
    float* sW    = sm + F_W;      // [4*RPAD][KD], zero-padded
    float* sH    = sm + F_H;      // SUBS x 2 x [EPS][HSTR]
    float* sBias = sm + F_BIAS;   // [4*RPAD]
    float* sWih  = sm + F_WIH;    // [4*RPAD]
    float* sWl   = sm + F_WL;
    float* sBl   = sm + F_BL;

    const int tid = threadIdx.x;

    // ---- cooperative staging ----
    for (int i = tid; i < FW_SZ; i += NTHR) {
        const int row = i / KD, k = i - row * KD;
        const int gate = row / RPAD, u = row - gate * RPAD;
        sW[i] = (u < HID && k < HID) ? W_hh[(gate * HID + u) * HID + k] : 0.0f;
    }
    for (int i = tid; i < FH_SZ; i += NTHR) sH[i] = 0.0f;
    for (int i = tid; i < 4 * RPAD; i += NTHR) {
        const int gate = i / RPAD, u = i - gate * RPAD;
        const bool v = (u < HID);
        const int row = gate * HID + u;
        sBias[i] = v ? (b_ih[row] + b_hh[row]) : 0.0f;
        sWih[i]  = v ? W_ih[row] : 0.0f;        // I=1
    }
    if (tid < 52) sWl[tid] = (tid < HID) ? W_lin[tid] : 0.0f;
    if (tid == 0) sBl[0] = b_lin[0];
    __syncthreads();

    const int sub  = tid / SUBT;        // 0..3
    const int st   = tid - sub * SUBT;  // 0..223
    const int eIdx = st & (ET - 1);     // 0..7  (warp = 8e x 4u)
    const int u0   = (st >> 3) * NU;    // 0..54 even

    // x pointers for my ME=2 elements (clamped; stores guarded)
    const int e0 = blockIdx.x * EPB + sub * EPS + eIdx;  // m stride = 8
    const float* pX0 = x + (size_t)((e0     < B) ? e0     : 0) * T_LEN;
    const float* pX1 = x + (size_t)((e0 + 8 < B) ? e0 + 8 : 0) * T_LEN;

    float* sHsub = sH + sub * FH_SUB;

    float c[ME][NU];
#pragma unroll
    for (int m = 0; m < ME; m++)
#pragma unroll
        for (int s = 0; s < NU; s++) c[m][s] = 0.0f;

    const float L2E = 1.4426950408889634f;

    for (int t = 0; t < T_LEN; t++) {
        const float* hin  = sHsub + (t & 1) * (EPS * HSTR) + eIdx * HSTR;
        float*       hout = sHsub + ((t + 1) & 1) * (EPS * HSTR) + eIdx * HSTR;

        float xv[ME];
        xv[0] = __ldg(pX0 + t);
        xv[1] = __ldg(pX1 + t);

        // ---- 8x2 register tile over k, packed f32x2 (13 float4 chunks) ----
        unsigned long long acc[NROW][ME];
#pragma unroll
        for (int r = 0; r < NROW; r++)
#pragma unroll
            for (int m = 0; m < ME; m++) acc[r][m] = 0ull;

#pragma unroll
        for (int k4 = 0; k4 < KD / 4; k4++) {
            const ulonglong2 hv0 = *reinterpret_cast<const ulonglong2*>(
                hin + 4 * k4);
            const ulonglong2 hv1 = *reinterpret_cast<const ulonglong2*>(
                hin + 8 * HSTR + 4 * k4);
#pragma unroll
            for (int gate = 0; gate < 4; gate++) {
#pragma unroll
                for (int s = 0; s < NU; s++) {
                    const ulonglong2 wv = *reinterpret_cast<const ulonglong2*>(
                        sW + (gate * RPAD + u0 + s) * KD + 4 * k4);
                    const int r = gate * NU + s;
                    ffma2(acc[r][0], wv.x, hv0.x);
                    ffma2(acc[r][0], wv.y, hv0.y);
                    ffma2(acc[r][1], wv.x, hv1.x);
                    ffma2(acc[r][1], wv.y, hv1.y);
                }
            }
        }

        // ---- fused fold + activation + cell update (no act[] array) ----
#pragma unroll
        for (int m = 0; m < ME; m++) {
            float2 hnew;
#pragma unroll
            for (int s = 0; s < NU; s++) {
                float g4[4];
#pragma unroll
                for (int gate = 0; gate < 4; gate++) {
                    U64F2 u; u.u = acc[gate * NU + s][m];
                    const int bi = gate * RPAD + u0 + s;
                    const float pre = (u.f.x + u.f.y)
                                    + fmaf(xv[m], sWih[bi], sBias[bi]);
                    const float k1 = (gate == 2) ? (-2.0f * L2E) : (-L2E);
                    const float am = (gate == 2) ? 2.0f : 1.0f;
                    const float aa = (gate == 2) ? -1.0f : 0.0f;
                    const float e2 = fast_ex2(k1 * pre);
                    const float rr = fast_rcp(1.0f + e2);
                    g4[gate] = fmaf(am, rr, aa);
                }
                const float cj = fmaf(g4[1], c[m][s], g4[0] * g4[2]);
                c[m][s] = cj;
                const float e2 = fast_ex2(-2.0f * L2E * cj);
                const float rr = fast_rcp(1.0f + e2);
                const float hj = g4[3] * fmaf(2.0f, rr, -1.0f);
                (s == 0 ? hnew.x : hnew.y) = hj;
            }
            *reinterpret_cast<float2*>(hout + m * (8 * HSTR) + u0) = hnew;
        }

        // subgroup-scoped barrier: 7 warps, one per step
        asm volatile("bar.sync %0, %1;" :: "r"(sub + 1), "r"(SUBT) : "memory");
    }

    __syncthreads();   // cross-subgroup: head threads read other subs' sH

    // ---- head: h_T in buffer 0 (T even); one thread per element ----
    if (tid < EPB) {
        const int ge = blockIdx.x * EPB + tid;
        if (ge < B) {
            const int hsub = tid >> 4, el = tid & 15;
            const float* hrow = sH + hsub * FH_SUB + el * HSTR;  // buf 0
            float y = sBl[0];
#pragma unroll
            for (int j = 0; j < HID; j++) y = fmaf(hrow[j], sWl[j], y);
            out[ge] = y;
        }
    }
}

extern "C" void kernel_launch(void* const* d_in, const int* in_sizes, int n_in,
                              void* d_out, int out_size) {
    const float* x     = (const float*)d_in[0];
    const float* W_ih  = (const float*)d_in[1];
    const float* W_hh  = (const float*)d_in[2];
    const float* b_ih  = (const float*)d_in[3];
    const float* b_hh  = (const float*)d_in[4];
    const float* W_lin = (const float*)d_in[5];
    const float* b_lin = (const float*)d_in[6];
    float* out = (float*)d_out;

    const int B = out_size;                    // [B,1]
    const int blocks = (B + EPB - 1) / EPB;    // 128 for B=8192

    static int smem_set = 0;
    if (!smem_set) {
        cudaFuncSetAttribute(lstm_r15_kernel,
                             cudaFuncAttributeMaxDynamicSharedMemorySize,
                             SM_TOT);
        smem_set = 1;
    }
    lstm_r15_kernel<<<blocks, NTHR, SM_TOT>>>(x, W_ih, W_hh, b_ih, b_hh,
                                              W_lin, b_lin, out, B);
}